// round 4
// baseline (speedup 1.0000x reference)
#include <cuda_runtime.h>

#define NL 25
#define ED 64
#define HD 8
#define NB 1000
#define NS 512
#define CS 5          // CTAs (batch slices) per layer
#define BPC 200       // batches per CTA
#define TC 4          // time-steps per handshake chunk
#define NCH (NS / TC)

typedef unsigned long long u64;

// Scratch (static __device__ arrays; allocation-free per harness rules)
__device__ float g_xproj[NS * NB * 24];                    // layer-0 x-projections (+bias)
__device__ float g_hbuf[(NL - 1) * NS * NB * HD];          // inter-layer h buffers
__device__ unsigned int g_flags[(NL - 1) * NCH * NB];      // per-thread chunk flags

// ---------- f32x2 packed-FMA helpers ----------
__device__ __forceinline__ u64 pk2(float v) {
    u64 d; asm("mov.b64 %0,{%1,%1};" : "=l"(d) : "f"(v)); return d;
}
__device__ __forceinline__ u64 pkab(float a, float b) {
    u64 d; asm("mov.b64 %0,{%1,%2};" : "=l"(d) : "f"(a), "f"(b)); return d;
}
__device__ __forceinline__ void upk(u64 v, float& a, float& b) {
    asm("mov.b64 {%0,%1},%2;" : "=f"(a), "=f"(b) : "l"(v));
}
__device__ __forceinline__ u64 f2fma(u64 a, u64 b, u64 c) {
    u64 d; asm("fma.rn.f32x2 %0,%1,%2,%3;" : "=l"(d) : "l"(a), "l"(b), "l"(c)); return d;
}
__device__ __forceinline__ u64 f2add(u64 a, u64 b) {
    u64 d; asm("add.rn.f32x2 %0,%1,%2;" : "=l"(d) : "l"(a), "l"(b)); return d;
}
__device__ __forceinline__ void fma8p(u64* acc, u64 s2, const u64* w) {
    acc[0] = f2fma(s2, w[0], acc[0]); acc[1] = f2fma(s2, w[1], acc[1]);
    acc[2] = f2fma(s2, w[2], acc[2]); acc[3] = f2fma(s2, w[3], acc[3]);
}

// ---------- MUFU.TANH activations ----------
__device__ __forceinline__ float tanh_hw(float x) {
    float t; asm("tanh.approx.f32 %0,%1;" : "=f"(t) : "f"(x)); return t;
}
__device__ __forceinline__ float sigm(float x) {
    return fmaf(0.5f, tanh_hw(0.5f * x), 0.5f);
}

// ---------- precompute: layer-0 x-projections + flag clear ----------
__global__ void __launch_bounds__(256) precompute_xproj(
    const int* __restrict__ x, const float* __restrict__ emb,
    const float* __restrict__ Wxz0, const float* __restrict__ bz0,
    const float* __restrict__ Wxr0, const float* __restrict__ br0,
    const float* __restrict__ WxH0, const float* __restrict__ bH0)
{
    __shared__ __align__(16) float sw[3][ED][8];
    __shared__ __align__(16) float sb[24];
    const int tid = threadIdx.x;
    for (int i = tid; i < ED * HD; i += blockDim.x) {
        ((float*)sw[0])[i] = Wxz0[i];
        ((float*)sw[1])[i] = Wxr0[i];
        ((float*)sw[2])[i] = WxH0[i];
    }
    if (tid < 8) { sb[tid] = bz0[tid]; sb[8 + tid] = br0[tid]; sb[16 + tid] = bH0[tid]; }
    __syncthreads();

    const int gid = blockIdx.x * blockDim.x + tid;   // NB*NS = 512000 threads

    // clear chunk flags: 24*128*1000 u32 = 768000 uint4
    {
        uint4 z4 = make_uint4(0u, 0u, 0u, 0u);
        uint4* f4 = (uint4*)g_flags;
        const int nf4 = (NL - 1) * NCH * NB / 4;
        #pragma unroll
        for (int j = 0; j < 2; j++) {
            int idx = gid + j * (NB * NS);
            if (idx < nf4) f4[idx] = z4;
        }
    }

    if (gid >= NB * NS) return;
    const int b = gid / NS, t = gid % NS;
    const int idx = x[gid];
    const float4* e4 = (const float4*)(emb + (long long)idx * ED);

    const u64 (*wz)[4] = (const u64(*)[4])sw[0];
    const u64 (*wr)[4] = (const u64(*)[4])sw[1];
    const u64 (*wH)[4] = (const u64(*)[4])sw[2];
    const u64* sb2 = (const u64*)sb;

    u64 acc[12];
    #pragma unroll
    for (int j = 0; j < 12; j++) acc[j] = sb2[j];

    #pragma unroll
    for (int k4 = 0; k4 < ED / 4; k4++) {
        float4 ev = e4[k4];
        float es[4] = {ev.x, ev.y, ev.z, ev.w};
        #pragma unroll
        for (int q = 0; q < 4; q++) {
            const int k = k4 * 4 + q;
            const u64 s2 = pk2(es[q]);
            fma8p(acc,     s2, wz[k]);
            fma8p(acc + 4, s2, wr[k]);
            fma8p(acc + 8, s2, wH[k]);
        }
    }
    float o[24];
    #pragma unroll
    for (int j = 0; j < 12; j++) upk(acc[j], o[2 * j], o[2 * j + 1]);
    float4* o4 = (float4*)(g_xproj + ((long long)t * NB + b) * 24);
    #pragma unroll
    for (int j = 0; j < 6; j++)
        o4[j] = make_float4(o[4 * j], o[4 * j + 1], o[4 * j + 2], o[4 * j + 3]);
}

// ---------- persistent layer-pipelined GRU ----------
__global__ void __launch_bounds__(256, 1) gru_pipeline(
    const float* __restrict__ Whz0, const float* __restrict__ Whr0, const float* __restrict__ WrH0,
    const float* __restrict__ Wxz, const float* __restrict__ Whz, const float* __restrict__ bz,
    const float* __restrict__ Wxr, const float* __restrict__ Whr, const float* __restrict__ br,
    const float* __restrict__ WxH, const float* __restrict__ WrH, const float* __restrict__ bH,
    const float* __restrict__ Why, const float* __restrict__ by,
    float* __restrict__ out, int out_size)
{
    __shared__ __align__(16) float sw[6][HD][8];  // 0 Wxz | 1 Whz | 2 Wxr | 3 Whr | 4 WxH | 5 WrH
    __shared__ __align__(16) float sb[24];
    const int tid = threadIdx.x;
    const int layer = blockIdx.x / CS;
    const int c = blockIdx.x % CS;

    if (layer == 0) {
        for (int i = tid; i < HD * HD; i += blockDim.x) {
            ((float*)sw[0])[i] = Whz0[i];   // slot 0 = Whz0
            ((float*)sw[1])[i] = Whr0[i];   // slot 1 = Whr0
            ((float*)sw[2])[i] = WrH0[i];   // slot 2 = WrH0
        }
    } else {
        const int off = (layer - 1) * HD * HD;
        for (int i = tid; i < HD * HD; i += blockDim.x) {
            ((float*)sw[0])[i] = Wxz[off + i];
            ((float*)sw[1])[i] = Whz[off + i];
            ((float*)sw[2])[i] = Wxr[off + i];
            ((float*)sw[3])[i] = Whr[off + i];
            ((float*)sw[4])[i] = WxH[off + i];
            ((float*)sw[5])[i] = WrH[off + i];
        }
        if (tid < 8) {
            sb[tid]      = bz[(layer - 1) * 8 + tid];
            sb[8 + tid]  = br[(layer - 1) * 8 + tid];
            sb[16 + tid] = bH[(layer - 1) * 8 + tid];
        }
    }
    __syncthreads();
    if (tid >= BPC) return;

    const int b = c * BPC + tid;
    float h[8];
    #pragma unroll
    for (int j = 0; j < 8; j++) h[j] = 0.f;

    unsigned int* prodflag = (layer < NL - 1)
        ? g_flags + ((long long)layer * NCH) * NB + b : 0;
    float* outbase = (layer < NL - 1)
        ? g_hbuf + (((long long)layer * NS) * NB + b) * HD : 0;

    if (layer == 0) {
        // -------- layer 0: prefetched xproj stream, no polling --------
        const float4* xp = (const float4*)(g_xproj + (long long)b * 24);
        const u64 (*hz2)[4] = (const u64(*)[4])sw[0];
        const u64 (*hr2)[4] = (const u64(*)[4])sw[1];
        const u64 (*rH2)[4] = (const u64(*)[4])sw[2];

        float4 v[6];
        #pragma unroll
        for (int j = 0; j < 6; j++) v[j] = __ldcg(xp + j);

        #pragma unroll 1
        for (int t = 0; t < NS; t++) {
            float4 vn[6];
            if (t + 1 < NS) {
                const float4* xpn = (const float4*)(g_xproj + ((long long)(t + 1) * NB + b) * 24);
                #pragma unroll
                for (int j = 0; j < 6; j++) vn[j] = __ldcg(xpn + j);
            }
            u64 az[4], ar[4], aH[4];
            az[0] = pkab(v[0].x, v[0].y); az[1] = pkab(v[0].z, v[0].w);
            az[2] = pkab(v[1].x, v[1].y); az[3] = pkab(v[1].z, v[1].w);
            ar[0] = pkab(v[2].x, v[2].y); ar[1] = pkab(v[2].z, v[2].w);
            ar[2] = pkab(v[3].x, v[3].y); ar[3] = pkab(v[3].z, v[3].w);
            aH[0] = pkab(v[4].x, v[4].y); aH[1] = pkab(v[4].z, v[4].w);
            aH[2] = pkab(v[5].x, v[5].y); aH[3] = pkab(v[5].z, v[5].w);
            #pragma unroll
            for (int k = 0; k < 8; k++) {
                const u64 h2 = pk2(h[k]);
                fma8p(az, h2, hz2[k]);
                fma8p(ar, h2, hr2[k]);
            }
            float azf[8], arf[8], z[8], r[8];
            #pragma unroll
            for (int j = 0; j < 4; j++) { upk(az[j], azf[2*j], azf[2*j+1]);
                                          upk(ar[j], arf[2*j], arf[2*j+1]); }
            #pragma unroll
            for (int j = 0; j < 8; j++) { z[j] = sigm(azf[j]); r[j] = sigm(arf[j]); }
            #pragma unroll
            for (int k = 0; k < 8; k++) fma8p(aH, pk2(h[k] * r[k]), rH2[k]);
            float aHf[8];
            #pragma unroll
            for (int j = 0; j < 4; j++) upk(aH[j], aHf[2*j], aHf[2*j+1]);
            #pragma unroll
            for (int j = 0; j < 8; j++) {
                const float Hc = tanh_hw(aHf[j]);
                h[j] = fmaf(z[j], Hc - h[j], h[j]);
            }
            {
                float4* op = (float4*)(outbase + (long long)t * NB * HD);
                op[0] = make_float4(h[0], h[1], h[2], h[3]);
                op[1] = make_float4(h[4], h[5], h[6], h[7]);
                if ((t & (TC - 1)) == TC - 1) {
                    unsigned int* fp = prodflag + (long long)(t / TC) * NB;
                    asm volatile("st.global.release.gpu.b32 [%0], %1;"
                                 :: "l"(fp), "r"(1u) : "memory");
                }
            }
            #pragma unroll
            for (int j = 0; j < 6; j++) v[j] = vn[j];
        }
    } else {
        // -------- layers 1..24: chunked consume (poll once per TC steps) --------
        const u64 (*wxz2)[4] = (const u64(*)[4])sw[0];
        const u64 (*whz2)[4] = (const u64(*)[4])sw[1];
        const u64 (*wxr2)[4] = (const u64(*)[4])sw[2];
        const u64 (*whr2)[4] = (const u64(*)[4])sw[3];
        const u64 (*wxH2)[4] = (const u64(*)[4])sw[4];
        const u64 (*wrH2)[4] = (const u64(*)[4])sw[5];
        u64 bz2[4], br2[4], bH2[4];
        {
            const u64* sb2 = (const u64*)sb;
            #pragma unroll
            for (int j = 0; j < 4; j++) { bz2[j] = sb2[j]; br2[j] = sb2[4+j]; bH2[j] = sb2[8+j]; }
        }
        const unsigned int* consflag = g_flags + ((long long)(layer - 1) * NCH) * NB + b;
        const float* inbase = g_hbuf + (((long long)(layer - 1) * NS) * NB + b) * HD;
        const bool producer = (layer < NL - 1);

        #pragma unroll 1
        for (int tc = 0; tc < NS; tc += TC) {
            // h-part for first step of chunk — overlaps the poll below
            u64 az[4], ar[4], aH[4];
            #pragma unroll
            for (int j = 0; j < 4; j++) { az[j] = bz2[j]; ar[j] = br2[j]; }
            #pragma unroll
            for (int k = 0; k < 8; k++) {
                const u64 h2 = pk2(h[k]);
                fma8p(az, h2, whz2[k]);
                fma8p(ar, h2, whr2[k]);
            }
            // acquire-poll the chunk flag
            {
                const unsigned int* fp = consflag + (long long)(tc / TC) * NB;
                unsigned int f;
                do {
                    asm volatile("ld.global.acquire.gpu.b32 %0, [%1];"
                                 : "=r"(f) : "l"(fp) : "memory");
                } while (f == 0u);
            }
            // load all TC steps' inputs at once (MLP)
            float4 xa[TC][2];
            #pragma unroll
            for (int s = 0; s < TC; s++) {
                const float4* xi = (const float4*)(inbase + (long long)(tc + s) * NB * HD);
                xa[s][0] = __ldcg(xi);
                xa[s][1] = __ldcg(xi + 1);
            }
            #pragma unroll
            for (int s = 0; s < TC; s++) {
                if (s > 0) {
                    #pragma unroll
                    for (int j = 0; j < 4; j++) { az[j] = bz2[j]; ar[j] = br2[j]; }
                    #pragma unroll
                    for (int k = 0; k < 8; k++) {
                        const u64 h2 = pk2(h[k]);
                        fma8p(az, h2, whz2[k]);
                        fma8p(ar, h2, whr2[k]);
                    }
                }
                #pragma unroll
                for (int j = 0; j < 4; j++) aH[j] = bH2[j];
                const float xk[8] = {xa[s][0].x, xa[s][0].y, xa[s][0].z, xa[s][0].w,
                                     xa[s][1].x, xa[s][1].y, xa[s][1].z, xa[s][1].w};
                #pragma unroll
                for (int k = 0; k < 8; k++) {
                    const u64 x2 = pk2(xk[k]);
                    fma8p(az, x2, wxz2[k]);
                    fma8p(ar, x2, wxr2[k]);
                    fma8p(aH, x2, wxH2[k]);
                }
                float azf[8], arf[8], z[8], r[8];
                #pragma unroll
                for (int j = 0; j < 4; j++) { upk(az[j], azf[2*j], azf[2*j+1]);
                                              upk(ar[j], arf[2*j], arf[2*j+1]); }
                #pragma unroll
                for (int j = 0; j < 8; j++) { z[j] = sigm(azf[j]); r[j] = sigm(arf[j]); }
                #pragma unroll
                for (int k = 0; k < 8; k++) fma8p(aH, pk2(h[k] * r[k]), wrH2[k]);
                float aHf[8];
                #pragma unroll
                for (int j = 0; j < 4; j++) upk(aH[j], aHf[2*j], aHf[2*j+1]);
                #pragma unroll
                for (int j = 0; j < 8; j++) {
                    const float Hc = tanh_hw(aHf[j]);
                    h[j] = fmaf(z[j], Hc - h[j], h[j]);
                }
                if (producer) {
                    float4* op = (float4*)(outbase + (long long)(tc + s) * NB * HD);
                    op[0] = make_float4(h[0], h[1], h[2], h[3]);
                    op[1] = make_float4(h[4], h[5], h[6], h[7]);
                }
            }
            if (producer) {
                unsigned int* fp = prodflag + (long long)(tc / TC) * NB;
                asm volatile("st.global.release.gpu.b32 [%0], %1;"
                             :: "l"(fp), "r"(1u) : "memory");
            }
        }
    }

    if (out_size >= NB + NL * NB * HD) {
        float4* hp = (float4*)(out + NB + ((long long)layer * NB + b) * HD);
        hp[0] = make_float4(h[0], h[1], h[2], h[3]);
        hp[1] = make_float4(h[4], h[5], h[6], h[7]);
    }
    if (layer == NL - 1) {
        float acc = by[0];
        #pragma unroll
        for (int j = 0; j < 8; j++) acc = fmaf(h[j], Why[j], acc);
        out[b] = acc;
    }
}

extern "C" void kernel_launch(void* const* d_in, const int* in_sizes, int n_in,
                              void* d_out, int out_size) {
    const int*   x    = (const int*)d_in[0];
    const float* emb  = (const float*)d_in[1];
    const float* Wxz0 = (const float*)d_in[2];
    const float* Whz0 = (const float*)d_in[3];
    const float* bz0  = (const float*)d_in[4];
    const float* Wxr0 = (const float*)d_in[5];
    const float* Whr0 = (const float*)d_in[6];
    const float* br0  = (const float*)d_in[7];
    const float* WxH0 = (const float*)d_in[8];
    const float* WrH0 = (const float*)d_in[9];
    const float* bH0  = (const float*)d_in[10];
    const float* Wxz  = (const float*)d_in[11];
    const float* Whz  = (const float*)d_in[12];
    const float* bz   = (const float*)d_in[13];
    const float* Wxr  = (const float*)d_in[14];
    const float* Whr  = (const float*)d_in[15];
    const float* br   = (const float*)d_in[16];
    const float* WxH  = (const float*)d_in[17];
    const float* WrH  = (const float*)d_in[18];
    const float* bH   = (const float*)d_in[19];
    const float* Why  = (const float*)d_in[20];
    const float* by   = (const float*)d_in[21];
    float* out = (float*)d_out;

    precompute_xproj<<<(NB * NS + 255) / 256, 256>>>(x, emb, Wxz0, bz0, Wxr0, br0, WxH0, bH0);
    gru_pipeline<<<NL * CS, 256>>>(Whz0, Whr0, WrH0,
                                   Wxz, Whz, bz, Wxr, Whr, br, WxH, WrH, bH,
                                   Why, by, out, out_size);
}

// round 6
// speedup vs baseline: 1.2988x; 1.2988x over previous
#include <cuda_runtime.h>

#define NL 25
#define ED 64
#define HD 8
#define NB 1000
#define NS 512
#define CS 5          // CTAs (batch slices) per layer
#define BPC 200       // batches per CTA

typedef unsigned long long u64;

// Scratch (static __device__ arrays; allocation-free per harness rules)
__device__ float g_xproj[NS * NB * 24];                    // layer-0 x-projections (+bias)
__device__ float g_hbuf[(NL - 1) * NS * NB * HD];          // inter-layer h buffers
__device__ unsigned int g_flags[(NL - 1) * NS * NB];       // per-thread per-step flags

// ---------- f32x2 packed-FMA helpers ----------
__device__ __forceinline__ u64 pk2(float v) {
    u64 d; asm("mov.b64 %0,{%1,%1};" : "=l"(d) : "f"(v)); return d;
}
__device__ __forceinline__ u64 pkab(float a, float b) {
    u64 d; asm("mov.b64 %0,{%1,%2};" : "=l"(d) : "f"(a), "f"(b)); return d;
}
__device__ __forceinline__ void upk(u64 v, float& a, float& b) {
    asm("mov.b64 {%0,%1},%2;" : "=f"(a), "=f"(b) : "l"(v));
}
__device__ __forceinline__ u64 f2fma(u64 a, u64 b, u64 c) {
    u64 d; asm("fma.rn.f32x2 %0,%1,%2,%3;" : "=l"(d) : "l"(a), "l"(b), "l"(c)); return d;
}
// acc[0..3] += s2 * wrow[0..7]  (weight row read as 2x LDS.128)
__device__ __forceinline__ void fma8w(u64* acc, u64 s2, const float* wrow) {
    ulonglong2 w01 = *(const ulonglong2*)(wrow);
    ulonglong2 w23 = *(const ulonglong2*)(wrow + 4);
    acc[0] = f2fma(s2, w01.x, acc[0]); acc[1] = f2fma(s2, w01.y, acc[1]);
    acc[2] = f2fma(s2, w23.x, acc[2]); acc[3] = f2fma(s2, w23.y, acc[3]);
}

// ---------- MUFU.TANH activations ----------
__device__ __forceinline__ float tanh_hw(float x) {
    float t; asm("tanh.approx.f32 %0,%1;" : "=f"(t) : "f"(x)); return t;
}
__device__ __forceinline__ float sigm(float x) {
    return fmaf(0.5f, tanh_hw(0.5f * x), 0.5f);
}

// ---------- precompute: layer-0 x-projections + flag clear ----------
__global__ void __launch_bounds__(256) precompute_xproj(
    const int* __restrict__ x, const float* __restrict__ emb,
    const float* __restrict__ Wxz0, const float* __restrict__ bz0,
    const float* __restrict__ Wxr0, const float* __restrict__ br0,
    const float* __restrict__ WxH0, const float* __restrict__ bH0)
{
    __shared__ __align__(16) float sw[3][ED][8];
    __shared__ __align__(16) float sb[24];
    const int tid = threadIdx.x;
    for (int i = tid; i < ED * HD; i += blockDim.x) {
        ((float*)sw[0])[i] = Wxz0[i];
        ((float*)sw[1])[i] = Wxr0[i];
        ((float*)sw[2])[i] = WxH0[i];
    }
    if (tid < 8) { sb[tid] = bz0[tid]; sb[8 + tid] = br0[tid]; sb[16 + tid] = bH0[tid]; }
    __syncthreads();

    const int gid = blockIdx.x * blockDim.x + tid;   // NB*NS = 512000 threads

    // clear flags: 24*512*1000 u32 = 3,072,000 uint4
    {
        uint4 z4 = make_uint4(0u, 0u, 0u, 0u);
        uint4* f4 = (uint4*)g_flags;
        #pragma unroll
        for (int j = 0; j < 6; j++) f4[gid + j * (NB * NS)] = z4;
    }

    if (gid >= NB * NS) return;
    const int b = gid / NS, t = gid % NS;
    const int idx = x[gid];
    const float4* e4 = (const float4*)(emb + (long long)idx * ED);

    const u64* sb2 = (const u64*)sb;
    u64 acc[12];
    #pragma unroll
    for (int j = 0; j < 12; j++) acc[j] = sb2[j];

    #pragma unroll
    for (int k4 = 0; k4 < ED / 4; k4++) {
        float4 ev = e4[k4];
        float es[4] = {ev.x, ev.y, ev.z, ev.w};
        #pragma unroll
        for (int q = 0; q < 4; q++) {
            const int k = k4 * 4 + q;
            const u64 s2 = pk2(es[q]);
            fma8w(acc,     s2, sw[0][k]);
            fma8w(acc + 4, s2, sw[1][k]);
            fma8w(acc + 8, s2, sw[2][k]);
        }
    }
    float o[24];
    #pragma unroll
    for (int j = 0; j < 12; j++) upk(acc[j], o[2 * j], o[2 * j + 1]);
    float4* o4 = (float4*)(g_xproj + ((long long)t * NB + b) * 24);
    #pragma unroll
    for (int j = 0; j < 6; j++)
        o4[j] = make_float4(o[4 * j], o[4 * j + 1], o[4 * j + 2], o[4 * j + 3]);
}

// ---------- persistent layer-pipelined GRU ----------
// blockIdx = layer*CS + slice. Depth-1 software pipeline: poll+load step t+1
// before computing step t; producers run ahead so the poll is usually a hit.
__global__ void __launch_bounds__(256, 1) gru_pipeline(
    const float* __restrict__ Whz0, const float* __restrict__ Whr0, const float* __restrict__ WrH0,
    const float* __restrict__ Wxz, const float* __restrict__ Whz, const float* __restrict__ bz,
    const float* __restrict__ Wxr, const float* __restrict__ Whr, const float* __restrict__ br,
    const float* __restrict__ WxH, const float* __restrict__ WrH, const float* __restrict__ bH,
    const float* __restrict__ Why, const float* __restrict__ by,
    float* __restrict__ out, int out_size)
{
    __shared__ __align__(16) float sw[6][HD][8];  // 0 Wxz | 1 Whz | 2 Wxr | 3 Whr | 4 WxH | 5 WrH
    __shared__ __align__(16) float sb[24];
    const int tid = threadIdx.x;
    const int layer = blockIdx.x / CS;
    const int c = blockIdx.x % CS;

    if (layer == 0) {
        for (int i = tid; i < HD * HD; i += blockDim.x) {
            ((float*)sw[0])[i] = Whz0[i];   // slot 0 = Whz0
            ((float*)sw[1])[i] = Whr0[i];   // slot 1 = Whr0
            ((float*)sw[2])[i] = WrH0[i];   // slot 2 = WrH0
        }
    } else {
        const int off = (layer - 1) * HD * HD;
        for (int i = tid; i < HD * HD; i += blockDim.x) {
            ((float*)sw[0])[i] = Wxz[off + i];
            ((float*)sw[1])[i] = Whz[off + i];
            ((float*)sw[2])[i] = Wxr[off + i];
            ((float*)sw[3])[i] = Whr[off + i];
            ((float*)sw[4])[i] = WxH[off + i];
            ((float*)sw[5])[i] = WrH[off + i];
        }
        if (tid < 8) {
            sb[tid]      = bz[(layer - 1) * 8 + tid];
            sb[8 + tid]  = br[(layer - 1) * 8 + tid];
            sb[16 + tid] = bH[(layer - 1) * 8 + tid];
        }
    }
    __syncthreads();
    if (tid >= BPC) return;

    const int b = c * BPC + tid;
    float h[8];
    #pragma unroll
    for (int j = 0; j < 8; j++) h[j] = 0.f;

    unsigned int* prodflag = (layer < NL - 1)
        ? g_flags + ((long long)layer * NS) * NB + b : 0;
    float* outbase = (layer < NL - 1)
        ? g_hbuf + (((long long)layer * NS) * NB + b) * HD : 0;

    if (layer == 0) {
        // -------- layer 0: prefetched xproj stream, no polling --------
        float4 v[6];
        {
            const float4* xp = (const float4*)(g_xproj + (long long)b * 24);
            #pragma unroll
            for (int j = 0; j < 6; j++) v[j] = __ldcg(xp + j);
        }
        #pragma unroll 1
        for (int t = 0; t < NS; t++) {
            float4 vn[6];
            if (t + 1 < NS) {
                const float4* xpn = (const float4*)(g_xproj + ((long long)(t + 1) * NB + b) * 24);
                #pragma unroll
                for (int j = 0; j < 6; j++) vn[j] = __ldcg(xpn + j);
            }
            u64 az[4], ar[4], aH[4];
            az[0] = pkab(v[0].x, v[0].y); az[1] = pkab(v[0].z, v[0].w);
            az[2] = pkab(v[1].x, v[1].y); az[3] = pkab(v[1].z, v[1].w);
            ar[0] = pkab(v[2].x, v[2].y); ar[1] = pkab(v[2].z, v[2].w);
            ar[2] = pkab(v[3].x, v[3].y); ar[3] = pkab(v[3].z, v[3].w);
            aH[0] = pkab(v[4].x, v[4].y); aH[1] = pkab(v[4].z, v[4].w);
            aH[2] = pkab(v[5].x, v[5].y); aH[3] = pkab(v[5].z, v[5].w);
            #pragma unroll
            for (int k = 0; k < 8; k++) {
                const u64 h2 = pk2(h[k]);
                fma8w(az, h2, sw[0][k]);
                fma8w(ar, h2, sw[1][k]);
            }
            float azf[8], arf[8], z[8], r[8];
            #pragma unroll
            for (int j = 0; j < 4; j++) { upk(az[j], azf[2*j], azf[2*j+1]);
                                          upk(ar[j], arf[2*j], arf[2*j+1]); }
            #pragma unroll
            for (int j = 0; j < 8; j++) { z[j] = sigm(azf[j]); r[j] = sigm(arf[j]); }
            #pragma unroll
            for (int k = 0; k < 8; k++) fma8w(aH, pk2(h[k] * r[k]), sw[2][k]);
            float aHf[8];
            #pragma unroll
            for (int j = 0; j < 4; j++) upk(aH[j], aHf[2*j], aHf[2*j+1]);
            #pragma unroll
            for (int j = 0; j < 8; j++) {
                const float Hc = tanh_hw(aHf[j]);
                h[j] = fmaf(z[j], Hc - h[j], h[j]);
            }
            {
                float4* op = (float4*)(outbase + (long long)t * NB * HD);
                op[0] = make_float4(h[0], h[1], h[2], h[3]);
                op[1] = make_float4(h[4], h[5], h[6], h[7]);
                unsigned int* fp = prodflag + (long long)t * NB;
                asm volatile("st.global.release.gpu.b32 [%0], %1;"
                             :: "l"(fp), "r"(1u) : "memory");
            }
            #pragma unroll
            for (int j = 0; j < 6; j++) v[j] = vn[j];
        }
    } else {
        // -------- layers 1..24: depth-1 prefetch consume --------
        u64 bz2[4], br2[4], bH2[4];
        {
            const u64* sb2 = (const u64*)sb;
            #pragma unroll
            for (int j = 0; j < 4; j++) { bz2[j] = sb2[j]; br2[j] = sb2[4+j]; bH2[j] = sb2[8+j]; }
        }
        const unsigned int* consflag = g_flags + ((long long)(layer - 1) * NS) * NB + b;
        const float* inbase = g_hbuf + (((long long)(layer - 1) * NS) * NB + b) * HD;
        const bool producer = (layer < NL - 1);

        // prologue: wait + load step 0
        float4 xa, xb;
        {
            unsigned int f;
            do {
                asm volatile("ld.global.acquire.gpu.b32 %0, [%1];"
                             : "=r"(f) : "l"(consflag) : "memory");
            } while (f == 0u);
            const float4* xi = (const float4*)inbase;
            xa = __ldcg(xi); xb = __ldcg(xi + 1);
        }

        #pragma unroll 1
        for (int t = 0; t < NS; t++) {
            // prefetch step t+1: poll (usually hit) then issue loads
            float4 nxa, nxb;
            if (t + 1 < NS) {
                const unsigned int* fp = consflag + (long long)(t + 1) * NB;
                unsigned int f;
                do {
                    asm volatile("ld.global.acquire.gpu.b32 %0, [%1];"
                                 : "=r"(f) : "l"(fp) : "memory");
                } while (f == 0u);
                const float4* xi = (const float4*)(inbase + (long long)(t + 1) * NB * HD);
                nxa = __ldcg(xi); nxb = __ldcg(xi + 1);
            }
            // compute step t with xa/xb
            u64 az[4], ar[4], aH[4];
            #pragma unroll
            for (int j = 0; j < 4; j++) { az[j] = bz2[j]; ar[j] = br2[j]; aH[j] = bH2[j]; }
            const float xk[8] = {xa.x, xa.y, xa.z, xa.w, xb.x, xb.y, xb.z, xb.w};
            #pragma unroll
            for (int k = 0; k < 8; k++) {
                const u64 x2 = pk2(xk[k]);
                const u64 h2 = pk2(h[k]);
                fma8w(az, x2, sw[0][k]);
                fma8w(az, h2, sw[1][k]);
                fma8w(ar, x2, sw[2][k]);
                fma8w(ar, h2, sw[3][k]);
                fma8w(aH, x2, sw[4][k]);
            }
            float azf[8], arf[8], z[8], r[8];
            #pragma unroll
            for (int j = 0; j < 4; j++) { upk(az[j], azf[2*j], azf[2*j+1]);
                                          upk(ar[j], arf[2*j], arf[2*j+1]); }
            #pragma unroll
            for (int j = 0; j < 8; j++) { z[j] = sigm(azf[j]); r[j] = sigm(arf[j]); }
            #pragma unroll
            for (int k = 0; k < 8; k++) fma8w(aH, pk2(h[k] * r[k]), sw[5][k]);
            float aHf[8];
            #pragma unroll
            for (int j = 0; j < 4; j++) upk(aH[j], aHf[2*j], aHf[2*j+1]);
            #pragma unroll
            for (int j = 0; j < 8; j++) {
                const float Hc = tanh_hw(aHf[j]);
                h[j] = fmaf(z[j], Hc - h[j], h[j]);
            }
            if (producer) {
                float4* op = (float4*)(outbase + (long long)t * NB * HD);
                op[0] = make_float4(h[0], h[1], h[2], h[3]);
                op[1] = make_float4(h[4], h[5], h[6], h[7]);
                unsigned int* fp = prodflag + (long long)t * NB;
                asm volatile("st.global.release.gpu.b32 [%0], %1;"
                             :: "l"(fp), "r"(1u) : "memory");
            }
            xa = nxa; xb = nxb;
        }
    }

    if (out_size >= NB + NL * NB * HD) {
        float4* hp = (float4*)(out + NB + ((long long)layer * NB + b) * HD);
        hp[0] = make_float4(h[0], h[1], h[2], h[3]);
        hp[1] = make_float4(h[4], h[5], h[6], h[7]);
    }
    if (layer == NL - 1) {
        float acc = by[0];
        #pragma unroll
        for (int j = 0; j < 8; j++) acc = fmaf(h[j], Why[j], acc);
        out[b] = acc;
    }
}

extern "C" void kernel_launch(void* const* d_in, const int* in_sizes, int n_in,
                              void* d_out, int out_size) {
    const int*   x    = (const int*)d_in[0];
    const float* emb  = (const float*)d_in[1];
    const float* Wxz0 = (const float*)d_in[2];
    const float* Whz0 = (const float*)d_in[3];
    const float* bz0  = (const float*)d_in[4];
    const float* Wxr0 = (const float*)d_in[5];
    const float* Whr0 = (const float*)d_in[6];
    const float* br0  = (const float*)d_in[7];
    const float* WxH0 = (const float*)d_in[8];
    const float* WrH0 = (const float*)d_in[9];
    const float* bH0  = (const float*)d_in[10];
    const float* Wxz  = (const float*)d_in[11];
    const float* Whz  = (const float*)d_in[12];
    const float* bz   = (const float*)d_in[13];
    const float* Wxr  = (const float*)d_in[14];
    const float* Whr  = (const float*)d_in[15];
    const float* br   = (const float*)d_in[16];
    const float* WxH  = (const float*)d_in[17];
    const float* WrH  = (const float*)d_in[18];
    const float* bH   = (const float*)d_in[19];
    const float* Why  = (const float*)d_in[20];
    const float* by   = (const float*)d_in[21];
    float* out = (float*)d_out;

    precompute_xproj<<<(NB * NS + 255) / 256, 256>>>(x, emb, Wxz0, bz0, Wxr0, br0, WxH0, bH0);
    gru_pipeline<<<NL * CS, 256>>>(Whz0, Whr0, WrH0,
                                   Wxz, Whz, bz, Wxr, Whr, br, WxH, WrH, bH,
                                   Why, by, out, out_size);
}

// round 7
// speedup vs baseline: 1.5442x; 1.1889x over previous
#include <cuda_runtime.h>

#define NL 25
#define ED 64
#define HD 8
#define NB 1000
#define NS 512
#define CS 5          // CTAs (batch slices) per layer
#define BPC 200       // batches per CTA

typedef unsigned long long u64;

// Scratch (static __device__ arrays; allocation-free per harness rules)
__device__ float g_xproj[NS * NB * 24];                    // layer-0 x-projections (+bias)
__device__ float g_hbuf[(NL - 1) * NS * NB * HD];          // inter-layer h buffers
__device__ unsigned int g_cnt[(NL - 1) * NB];              // per-(layer,b) progress counters

// ---------- f32x2 packed-FMA helpers ----------
__device__ __forceinline__ u64 pk2(float v) {
    u64 d; asm("mov.b64 %0,{%1,%1};" : "=l"(d) : "f"(v)); return d;
}
__device__ __forceinline__ u64 pkab(float a, float b) {
    u64 d; asm("mov.b64 %0,{%1,%2};" : "=l"(d) : "f"(a), "f"(b)); return d;
}
__device__ __forceinline__ void upk(u64 v, float& a, float& b) {
    asm("mov.b64 {%0,%1},%2;" : "=f"(a), "=f"(b) : "l"(v));
}
__device__ __forceinline__ u64 f2fma(u64 a, u64 b, u64 c) {
    u64 d; asm("fma.rn.f32x2 %0,%1,%2,%3;" : "=l"(d) : "l"(a), "l"(b), "l"(c)); return d;
}
// acc[0..3] += s2 * wrow[0..7]  (weight row read as 2x LDS.128)
__device__ __forceinline__ void fma8w(u64* acc, u64 s2, const float* wrow) {
    ulonglong2 w01 = *(const ulonglong2*)(wrow);
    ulonglong2 w23 = *(const ulonglong2*)(wrow + 4);
    acc[0] = f2fma(s2, w01.x, acc[0]); acc[1] = f2fma(s2, w01.y, acc[1]);
    acc[2] = f2fma(s2, w23.x, acc[2]); acc[3] = f2fma(s2, w23.y, acc[3]);
}

// ---------- MUFU.TANH activations ----------
__device__ __forceinline__ float tanh_hw(float x) {
    float t; asm("tanh.approx.f32 %0,%1;" : "=f"(t) : "f"(x)); return t;
}
__device__ __forceinline__ float sigm(float x) {
    return fmaf(0.5f, tanh_hw(0.5f * x), 0.5f);
}

// ---------- precompute: layer-0 x-projections + counter clear ----------
__global__ void __launch_bounds__(256) precompute_xproj(
    const int* __restrict__ x, const float* __restrict__ emb,
    const float* __restrict__ Wxz0, const float* __restrict__ bz0,
    const float* __restrict__ Wxr0, const float* __restrict__ br0,
    const float* __restrict__ WxH0, const float* __restrict__ bH0)
{
    __shared__ __align__(16) float sw[3][ED][8];
    __shared__ __align__(16) float sb[24];
    const int tid = threadIdx.x;
    for (int i = tid; i < ED * HD; i += blockDim.x) {
        ((float*)sw[0])[i] = Wxz0[i];
        ((float*)sw[1])[i] = Wxr0[i];
        ((float*)sw[2])[i] = WxH0[i];
    }
    if (tid < 8) { sb[tid] = bz0[tid]; sb[8 + tid] = br0[tid]; sb[16 + tid] = bH0[tid]; }
    __syncthreads();

    const int gid = blockIdx.x * blockDim.x + tid;   // NB*NS = 512000 threads

    // clear counters: (NL-1)*NB = 24000 u32 = 6000 uint4
    if (gid < (NL - 1) * NB / 4) {
        ((uint4*)g_cnt)[gid] = make_uint4(0u, 0u, 0u, 0u);
    }

    if (gid >= NB * NS) return;
    const int b = gid / NS, t = gid % NS;
    const int idx = x[gid];
    const float4* e4 = (const float4*)(emb + (long long)idx * ED);

    const u64* sb2 = (const u64*)sb;
    u64 acc[12];
    #pragma unroll
    for (int j = 0; j < 12; j++) acc[j] = sb2[j];

    #pragma unroll
    for (int k4 = 0; k4 < ED / 4; k4++) {
        float4 ev = e4[k4];
        float es[4] = {ev.x, ev.y, ev.z, ev.w};
        #pragma unroll
        for (int q = 0; q < 4; q++) {
            const int k = k4 * 4 + q;
            const u64 s2 = pk2(es[q]);
            fma8w(acc,     s2, sw[0][k]);
            fma8w(acc + 4, s2, sw[1][k]);
            fma8w(acc + 8, s2, sw[2][k]);
        }
    }
    float o[24];
    #pragma unroll
    for (int j = 0; j < 12; j++) upk(acc[j], o[2 * j], o[2 * j + 1]);
    float4* o4 = (float4*)(g_xproj + ((long long)t * NB + b) * 24);
    #pragma unroll
    for (int j = 0; j < 6; j++)
        o4[j] = make_float4(o[4 * j], o[4 * j + 1], o[4 * j + 2], o[4 * j + 3]);
}

// ---------- persistent layer-pipelined GRU ----------
// blockIdx = layer*CS + slice. Watermark counters amortize sync; x-parts of
// step t+1 are computed ahead of step t's h-dependent chain.
__global__ void __launch_bounds__(256, 1) gru_pipeline(
    const float* __restrict__ Whz0, const float* __restrict__ Whr0, const float* __restrict__ WrH0,
    const float* __restrict__ Wxz, const float* __restrict__ Whz, const float* __restrict__ bz,
    const float* __restrict__ Wxr, const float* __restrict__ Whr, const float* __restrict__ br,
    const float* __restrict__ WxH, const float* __restrict__ WrH, const float* __restrict__ bH,
    const float* __restrict__ Why, const float* __restrict__ by,
    float* __restrict__ out, int out_size)
{
    __shared__ __align__(16) float sw[6][HD][8];  // 0 Wxz | 1 Whz | 2 Wxr | 3 Whr | 4 WxH | 5 WrH
    __shared__ __align__(16) float sb[24];
    const int tid = threadIdx.x;
    const int layer = blockIdx.x / CS;
    const int c = blockIdx.x % CS;

    if (layer == 0) {
        for (int i = tid; i < HD * HD; i += blockDim.x) {
            ((float*)sw[0])[i] = Whz0[i];   // slot 0 = Whz0
            ((float*)sw[1])[i] = Whr0[i];   // slot 1 = Whr0
            ((float*)sw[2])[i] = WrH0[i];   // slot 2 = WrH0
        }
    } else {
        const int off = (layer - 1) * HD * HD;
        for (int i = tid; i < HD * HD; i += blockDim.x) {
            ((float*)sw[0])[i] = Wxz[off + i];
            ((float*)sw[1])[i] = Whz[off + i];
            ((float*)sw[2])[i] = Wxr[off + i];
            ((float*)sw[3])[i] = Whr[off + i];
            ((float*)sw[4])[i] = WxH[off + i];
            ((float*)sw[5])[i] = WrH[off + i];
        }
        if (tid < 8) {
            sb[tid]      = bz[(layer - 1) * 8 + tid];
            sb[8 + tid]  = br[(layer - 1) * 8 + tid];
            sb[16 + tid] = bH[(layer - 1) * 8 + tid];
        }
    }
    __syncthreads();
    if (tid >= BPC) return;

    const int b = c * BPC + tid;
    float h[8];
    #pragma unroll
    for (int j = 0; j < 8; j++) h[j] = 0.f;

    unsigned int* pcnt = (layer < NL - 1) ? g_cnt + layer * NB + b : 0;
    float* outbase = (layer < NL - 1)
        ? g_hbuf + (((long long)layer * NS) * NB + b) * HD : 0;

    if (layer == 0) {
        // -------- layer 0: prefetched xproj stream, no polling --------
        float4 v[6];
        {
            const float4* xp = (const float4*)(g_xproj + (long long)b * 24);
            #pragma unroll
            for (int j = 0; j < 6; j++) v[j] = __ldcg(xp + j);
        }
        #pragma unroll 1
        for (int t = 0; t < NS; t++) {
            float4 vn[6];
            if (t + 1 < NS) {
                const float4* xpn = (const float4*)(g_xproj + ((long long)(t + 1) * NB + b) * 24);
                #pragma unroll
                for (int j = 0; j < 6; j++) vn[j] = __ldcg(xpn + j);
            }
            u64 az[4], ar[4], aH[4];
            az[0] = pkab(v[0].x, v[0].y); az[1] = pkab(v[0].z, v[0].w);
            az[2] = pkab(v[1].x, v[1].y); az[3] = pkab(v[1].z, v[1].w);
            ar[0] = pkab(v[2].x, v[2].y); ar[1] = pkab(v[2].z, v[2].w);
            ar[2] = pkab(v[3].x, v[3].y); ar[3] = pkab(v[3].z, v[3].w);
            aH[0] = pkab(v[4].x, v[4].y); aH[1] = pkab(v[4].z, v[4].w);
            aH[2] = pkab(v[5].x, v[5].y); aH[3] = pkab(v[5].z, v[5].w);
            #pragma unroll
            for (int k = 0; k < 8; k++) {
                const u64 h2 = pk2(h[k]);
                fma8w(az, h2, sw[0][k]);
                fma8w(ar, h2, sw[1][k]);
            }
            float azf[8], arf[8], z[8], r[8];
            #pragma unroll
            for (int j = 0; j < 4; j++) { upk(az[j], azf[2*j], azf[2*j+1]);
                                          upk(ar[j], arf[2*j], arf[2*j+1]); }
            #pragma unroll
            for (int j = 0; j < 8; j++) { z[j] = sigm(azf[j]); r[j] = sigm(arf[j]); }
            #pragma unroll
            for (int k = 0; k < 8; k++) fma8w(aH, pk2(h[k] * r[k]), sw[2][k]);
            float aHf[8];
            #pragma unroll
            for (int j = 0; j < 4; j++) upk(aH[j], aHf[2*j], aHf[2*j+1]);
            #pragma unroll
            for (int j = 0; j < 8; j++) {
                const float Hc = tanh_hw(aHf[j]);
                h[j] = fmaf(z[j], Hc - h[j], h[j]);
            }
            {
                float4* op = (float4*)(outbase + (long long)t * NB * HD);
                op[0] = make_float4(h[0], h[1], h[2], h[3]);
                op[1] = make_float4(h[4], h[5], h[6], h[7]);
                asm volatile("st.global.release.gpu.b32 [%0], %1;"
                             :: "l"(pcnt), "r"((unsigned int)(t + 1)) : "memory");
            }
            #pragma unroll
            for (int j = 0; j < 6; j++) v[j] = vn[j];
        }
    } else {
        // -------- layers 1..24: watermark consume + x/h split --------
        u64 bz2[4], br2[4], bH2[4];
        {
            const u64* sb2 = (const u64*)sb;
            #pragma unroll
            for (int j = 0; j < 4; j++) { bz2[j] = sb2[j]; br2[j] = sb2[4+j]; bH2[j] = sb2[8+j]; }
        }
        const unsigned int* ccnt = g_cnt + (layer - 1) * NB + b;
        const float* inbase = g_hbuf + (((long long)(layer - 1) * NS) * NB + b) * HD;
        const bool producer = (layer < NL - 1);

        unsigned int avail = 0;
        auto wait_ge = [&](unsigned int want) {
            if (avail < want) {
                unsigned int vv;
                do {
                    asm volatile("ld.global.acquire.gpu.b32 %0, [%1];"
                                 : "=r"(vv) : "l"(ccnt) : "memory");
                } while (vv < want);
                avail = vv;
            }
        };

        // prologue: x(0) -> AX ; x(1) -> xn
        u64 AXz[4], AXr[4], AXH[4];
        float4 nxa, nxb;
        {
            wait_ge(1u);
            const float4* xi = (const float4*)inbase;
            float4 xa = __ldcg(xi), xb = __ldcg(xi + 1);
            const float xk[8] = {xa.x, xa.y, xa.z, xa.w, xb.x, xb.y, xb.z, xb.w};
            #pragma unroll
            for (int j = 0; j < 4; j++) { AXz[j] = bz2[j]; AXr[j] = br2[j]; AXH[j] = bH2[j]; }
            #pragma unroll
            for (int k = 0; k < 8; k++) {
                const u64 x2 = pk2(xk[k]);
                fma8w(AXz, x2, sw[0][k]);
                fma8w(AXr, x2, sw[2][k]);
                fma8w(AXH, x2, sw[4][k]);
            }
            wait_ge(2u);
            const float4* xi1 = (const float4*)(inbase + (long long)NB * HD);
            nxa = __ldcg(xi1); nxb = __ldcg(xi1 + 1);
        }

        #pragma unroll 1
        for (int t = 0; t < NS; t++) {
            // x-projections for step t+1 (independent of h)
            u64 NZ[4], NR[4], NH[4];
            if (t + 1 < NS) {
                const float xk[8] = {nxa.x, nxa.y, nxa.z, nxa.w, nxb.x, nxb.y, nxb.z, nxb.w};
                #pragma unroll
                for (int j = 0; j < 4; j++) { NZ[j] = bz2[j]; NR[j] = br2[j]; NH[j] = bH2[j]; }
                #pragma unroll
                for (int k = 0; k < 8; k++) {
                    const u64 x2 = pk2(xk[k]);
                    fma8w(NZ, x2, sw[0][k]);
                    fma8w(NR, x2, sw[2][k]);
                    fma8w(NH, x2, sw[4][k]);
                }
            }
            // watermark + prefetch x(t+2)
            float4 pxa, pxb;
            if (t + 2 < NS) {
                wait_ge((unsigned int)(t + 3));
                const float4* xi = (const float4*)(inbase + (long long)(t + 2) * NB * HD);
                pxa = __ldcg(xi); pxb = __ldcg(xi + 1);
            }
            // h-dependent part of step t
            u64 az[4], ar[4], aH[4];
            #pragma unroll
            for (int j = 0; j < 4; j++) { az[j] = AXz[j]; ar[j] = AXr[j]; aH[j] = AXH[j]; }
            #pragma unroll
            for (int k = 0; k < 8; k++) {
                const u64 h2 = pk2(h[k]);
                fma8w(az, h2, sw[1][k]);
                fma8w(ar, h2, sw[3][k]);
            }
            float azf[8], arf[8], z[8], r[8];
            #pragma unroll
            for (int j = 0; j < 4; j++) { upk(az[j], azf[2*j], azf[2*j+1]);
                                          upk(ar[j], arf[2*j], arf[2*j+1]); }
            #pragma unroll
            for (int j = 0; j < 8; j++) { z[j] = sigm(azf[j]); r[j] = sigm(arf[j]); }
            #pragma unroll
            for (int k = 0; k < 8; k++) fma8w(aH, pk2(h[k] * r[k]), sw[5][k]);
            float aHf[8];
            #pragma unroll
            for (int j = 0; j < 4; j++) upk(aH[j], aHf[2*j], aHf[2*j+1]);
            #pragma unroll
            for (int j = 0; j < 8; j++) {
                const float Hc = tanh_hw(aHf[j]);
                h[j] = fmaf(z[j], Hc - h[j], h[j]);
            }
            if (producer) {
                float4* op = (float4*)(outbase + (long long)t * NB * HD);
                op[0] = make_float4(h[0], h[1], h[2], h[3]);
                op[1] = make_float4(h[4], h[5], h[6], h[7]);
                asm volatile("st.global.release.gpu.b32 [%0], %1;"
                             :: "l"(pcnt), "r"((unsigned int)(t + 1)) : "memory");
            }
            // rotate pipeline state
            #pragma unroll
            for (int j = 0; j < 4; j++) { AXz[j] = NZ[j]; AXr[j] = NR[j]; AXH[j] = NH[j]; }
            nxa = pxa; nxb = pxb;
        }
    }

    if (out_size >= NB + NL * NB * HD) {
        float4* hp = (float4*)(out + NB + ((long long)layer * NB + b) * HD);
        hp[0] = make_float4(h[0], h[1], h[2], h[3]);
        hp[1] = make_float4(h[4], h[5], h[6], h[7]);
    }
    if (layer == NL - 1) {
        float acc = by[0];
        #pragma unroll
        for (int j = 0; j < 8; j++) acc = fmaf(h[j], Why[j], acc);
        out[b] = acc;
    }
}

extern "C" void kernel_launch(void* const* d_in, const int* in_sizes, int n_in,
                              void* d_out, int out_size) {
    const int*   x    = (const int*)d_in[0];
    const float* emb  = (const float*)d_in[1];
    const float* Wxz0 = (const float*)d_in[2];
    const float* Whz0 = (const float*)d_in[3];
    const float* bz0  = (const float*)d_in[4];
    const float* Wxr0 = (const float*)d_in[5];
    const float* Whr0 = (const float*)d_in[6];
    const float* br0  = (const float*)d_in[7];
    const float* WxH0 = (const float*)d_in[8];
    const float* WrH0 = (const float*)d_in[9];
    const float* bH0  = (const float*)d_in[10];
    const float* Wxz  = (const float*)d_in[11];
    const float* Whz  = (const float*)d_in[12];
    const float* bz   = (const float*)d_in[13];
    const float* Wxr  = (const float*)d_in[14];
    const float* Whr  = (const float*)d_in[15];
    const float* br   = (const float*)d_in[16];
    const float* WxH  = (const float*)d_in[17];
    const float* WrH  = (const float*)d_in[18];
    const float* bH   = (const float*)d_in[19];
    const float* Why  = (const float*)d_in[20];
    const float* by   = (const float*)d_in[21];
    float* out = (float*)d_out;

    precompute_xproj<<<(NB * NS + 255) / 256, 256>>>(x, emb, Wxz0, bz0, Wxr0, br0, WxH0, bH0);
    gru_pipeline<<<NL * CS, 256>>>(Whz0, Whr0, WrH0,
                                   Wxz, Whz, bz, Wxr, Whr, br, WxH, WrH, bH,
                                   Why, by, out, out_size);
}